// round 14
// baseline (speedup 1.0000x reference)
#include <cuda_runtime.h>
#include <math_constants.h>

#define BB 4
#define TT 4096
#define DD 1024
#define NROW (BB*TT)          // 16384

typedef unsigned long long u64;

// ---- scratch (device globals: no allocations allowed) ----
__device__ float2 g_Q[NROW];
__device__ float2 g_K[NROW];
__device__ unsigned long long g_best64[NROW]; // (ordered(score)<<32)|~s
__device__ int    g_idx[NROW];      // flattened source row b*T + argmax_s
__device__ int    g_mark[NROW];
__device__ int    g_slot[NROW];     // src row -> compact slot
__device__ int    g_list[NROW];
__device__ int    g_count;
__device__ float  g_Vc[(size_t)NROW * DD];  // compact V rows (slot-major)

static const unsigned FULL = 0xffffffffu;

__device__ __forceinline__ unsigned ord_f32(float x) {
    unsigned u = __float_as_uint(x);
    return (u & 0x80000000u) ? ~u : (u | 0x80000000u);
}

// packed 2x fp32 FMA (sm_103a FFMA2; PTX-only, ptxas won't auto-fuse)
__device__ __forceinline__ u64 fma2(u64 a, u64 b, u64 c) {
    u64 d;
    asm("fma.rn.f32x2 %0, %1, %2, %3;" : "=l"(d) : "l"(a), "l"(b), "l"(c));
    return d;
}
__device__ __forceinline__ float hadd2(u64 p) {
    float2 f;
    asm("mov.b64 {%0, %1}, %2;" : "=f"(f.x), "=f"(f.y) : "l"(p));
    return f.x + f.y;
}

// ---------------- kernel 1: Q,K projection (+ fused scratch init) ----------
__global__ void qk_kernel(const float* __restrict__ x,
                          const float* __restrict__ WQ,
                          const float* __restrict__ WK) {
    __shared__ float4 swq0[256], swq1[256], swk0[256], swk1[256];
    const float4* WQ4 = (const float4*)WQ;
    const float4* WK4 = (const float4*)WK;
    int tid = threadIdx.x;
    swq0[tid] = WQ4[tid];
    swq1[tid] = WQ4[256 + tid];
    swk0[tid] = WK4[tid];
    swk1[tid] = WK4[256 + tid];
    __syncthreads();

    int warp = tid >> 5, lane = tid & 31;
    int row = blockIdx.x * 8 + warp;           // b*T + t
    const float4* x4 = (const float4*)x + (size_t)row * 256;

    float q0 = 0.f, q1 = 0.f, k0 = 0.f, k1 = 0.f;
#pragma unroll
    for (int j = 0; j < 8; ++j) {
        int d = lane + j * 32;
        float4 xv = x4[d];
        float4 a = swq0[d], b = swq1[d], c = swk0[d], e = swk1[d];
        q0 += xv.x*a.x + xv.y*a.y + xv.z*a.z + xv.w*a.w;
        q1 += xv.x*b.x + xv.y*b.y + xv.z*b.z + xv.w*b.w;
        k0 += xv.x*c.x + xv.y*c.y + xv.z*c.z + xv.w*c.w;
        k1 += xv.x*e.x + xv.y*e.y + xv.z*e.z + xv.w*e.w;
    }
#pragma unroll
    for (int off = 16; off; off >>= 1) {
        q0 += __shfl_xor_sync(FULL, q0, off);
        q1 += __shfl_xor_sync(FULL, q1, off);
        k0 += __shfl_xor_sync(FULL, k0, off);
        k1 += __shfl_xor_sync(FULL, k1, off);
    }
    if (lane == 0) {
        g_Q[row] = make_float2(q0, q1);
        g_K[row] = make_float2(k0, k1);
        g_mark[row] = 0;
        g_best64[row] = 0ull;                  // < any real score encoding
        if (row == 0) g_count = 0;
    }
}

// ---------------- kernel 2: argmax, tile x chunk units (R7 exact) ----------
// Unit = (128-t tile, 1024-s chunk). 80 units/batch, grid (80, BB), 128 thr.
// Merge via atomicMax of (ordered(score)<<32)|~s  -> max score, min s on tie.
__global__ void __launch_bounds__(128) argmax_kernel() {
    __shared__ float2 ks[1024];    // 8 KB
    int b = blockIdx.y;
    int u = blockIdx.x, g = 0, base = 0;
    while (u >= base + 8 * (g + 1)) { base += 8 * (g + 1); ++g; }
    int r = u - base;
    int ti = g * 8 + r / (g + 1);
    int chunk = r % (g + 1);
    int t0 = ti * 128, s0 = chunk * 1024;

    const float4* K4 = (const float4*)(g_K + b * TT + s0);
#pragma unroll
    for (int j = 0; j < 4; ++j)
        ((float4*)ks)[threadIdx.x + j * 128] = K4[threadIdx.x + j * 128];
    __syncthreads();

    int t = t0 + threadIdx.x;
    float2 q = g_Q[b * TT + t];
    int s_limit = t - s0 + 1;
    if (s_limit > 1024) s_limit = 1024;

    float best = -CUDART_INF_F;
    int bi = 0;
    for (int s = 0; s < s_limit; ++s) {        // ascending + strict > = first occ.
        float2 k = ks[s];
        float sc = k.x * q.x + k.y * q.y;
        if (sc > best) { best = sc; bi = s0 + s; }
    }
    unsigned long long enc =
        ((unsigned long long)ord_f32(best) << 32) | (unsigned)(~bi);
    atomicMax(&g_best64[b * TT + t], enc);
}

// ---------------- kernel 2b: decode argmax + build unique list -------------
// Warp-dedup (__match_any_sync) + mark prefilter: few atomics instead of 16K
// funneling into hot addresses.
__global__ void decode_kernel() {
    int i = blockIdx.x * 256 + threadIdx.x;
    unsigned long long enc = g_best64[i];
    int s = (int)(~(unsigned)(enc & 0xffffffffull));
    int src = (i & ~(TT - 1)) | s;
    g_idx[i] = src;

    unsigned peers = __match_any_sync(FULL, src);
    int leader = __ffs(peers) - 1;
    if ((threadIdx.x & 31) == leader) {
        if (g_mark[src] == 0 && atomicExch(&g_mark[src], 1) == 0) {
            int p = atomicAdd(&g_count, 1);
            g_list[p] = src;
            g_slot[src] = p;                   // read only by later kernels
        }
    }
}

// ---------------- kernel 3: V rows, 4 rows x 4 e per warp, FFMA2 ----------
// Item = (4-row group, 32-e tile). Accumulators are f32x2 (even/odd k):
// per j-step 4 LDS.128 + 4 LDG.128 + 32 FFMA2 (was 64 FFMA) -> halves the
// fp32-pipe demand. One e-row of W_V = 1024 floats = 256 ulonglong2 (stride
// fixed from R13's *128 bug). Epilogue: unpack+FADD, 31-SHFL butterfly.
#define RG 4
__global__ void __launch_bounds__(256) vrows_kernel(const float* __restrict__ WV,
                                                    const float* __restrict__ x) {
    __shared__ float4 xs[RG * 256];            // 16 KB
    int cnt = g_count;
    int ngrp = (cnt + RG - 1) / RG;
    int items = ngrp * 32;                     // 32 e-tiles of 32
    int warp = threadIdx.x >> 5, lane = threadIdx.x & 31;
    int tid = threadIdx.x;

    for (int it = blockIdx.x; it < items; it += gridDim.x) {
        int grp  = it >> 5;                    // / 32
        int tile = it & 31;
        int ui0  = grp * RG;

        __syncthreads();                       // protect xs reuse
#pragma unroll
        for (int j = 0; j < 4; ++j) {          // 1024 float4 by 256 threads
            int f = tid + j * 256;
            int r = f >> 8, c = f & 255;
            int ui = ui0 + r;
            int row = g_list[(ui < cnt) ? ui : 0];
            xs[f] = ((const float4*)x)[(size_t)row * 256 + c];
        }
        __syncthreads();

        int e0 = tile * 32 + warp * 4;
        // one e-row = 1024 floats = 4096 B = 256 ulonglong2
        const ulonglong2* wp0 = (const ulonglong2*)WV + (size_t)(e0 + 0) * 256;
        const ulonglong2* wp1 = (const ulonglong2*)WV + (size_t)(e0 + 1) * 256;
        const ulonglong2* wp2 = (const ulonglong2*)WV + (size_t)(e0 + 2) * 256;
        const ulonglong2* wp3 = (const ulonglong2*)WV + (size_t)(e0 + 3) * 256;
        const ulonglong2* xs2 = (const ulonglong2*)xs;

        u64 acc[16];                           // f32x2 acc[r*4+e]
#pragma unroll
        for (int k = 0; k < 16; ++k) acc[k] = 0ull;

#pragma unroll
        for (int j = 0; j < 8; ++j) {
            int d = lane + j * 32;
            ulonglong2 w0 = wp0[d];
            ulonglong2 w1 = wp1[d];
            ulonglong2 w2 = wp2[d];
            ulonglong2 w3 = wp3[d];
#pragma unroll
            for (int r = 0; r < RG; ++r) {
                ulonglong2 xv = xs2[r * 256 + d];
                acc[r*4+0] = fma2(w0.x, xv.x, acc[r*4+0]);
                acc[r*4+1] = fma2(w1.x, xv.x, acc[r*4+1]);
                acc[r*4+2] = fma2(w2.x, xv.x, acc[r*4+2]);
                acc[r*4+3] = fma2(w3.x, xv.x, acc[r*4+3]);
                acc[r*4+0] = fma2(w0.y, xv.y, acc[r*4+0]);
                acc[r*4+1] = fma2(w1.y, xv.y, acc[r*4+1]);
                acc[r*4+2] = fma2(w2.y, xv.y, acc[r*4+2]);
                acc[r*4+3] = fma2(w3.y, xv.y, acc[r*4+3]);
            }
        }

        float a[16];
#pragma unroll
        for (int k = 0; k < 16; ++k) a[k] = hadd2(acc[k]);

        // butterfly: off=16 full-exchange on all 16, then distribute 16 values
        // over lanes (31 SHFL total). Lane l<16 ends with pair l.
#pragma unroll
        for (int i = 0; i < 16; ++i)
            a[i] += __shfl_xor_sync(FULL, a[i], 16);
#pragma unroll
        for (int off = 8; off; off >>= 1) {
#pragma unroll
            for (int i = 0; i < off; ++i) {
                float lo = a[i], hi = a[i + off];
                float mine = (lane & off) ? hi : lo;
                float send = (lane & off) ? lo : hi;
                float other = __shfl_xor_sync(FULL, send, off);
                a[i] = mine + other;
            }
        }

        if (lane < 16) {
            int r = lane >> 2, e = lane & 3;
            int ui = ui0 + r;
            if (ui < cnt)
                g_Vc[(size_t)ui * DD + e0 + e] = a[0];
        }
    }
}

// ---------------- kernel 4: gather to output ----------------
// Warp copies one 4KB row from compact (L2-resident) V; streaming stores.
__global__ void gather_kernel(float* __restrict__ out) {
    int warp = threadIdx.x >> 5, lane = threadIdx.x & 31;
    int r = blockIdx.x * 8 + warp;          // destination row b*T + t
    int slot = g_slot[g_idx[r]];
    const float4* v4 = (const float4*)g_Vc + (size_t)slot * 256;
    float4* o4 = (float4*)out + (size_t)r * 256;
#pragma unroll
    for (int j = 0; j < 8; ++j) {
        float4 v = __ldg(&v4[lane + j * 32]);
        __stcs(&o4[lane + j * 32], v);
    }
}

extern "C" void kernel_launch(void* const* d_in, const int* in_sizes, int n_in,
                              void* d_out, int out_size) {
    const float* x  = (const float*)d_in[0];
    const float* WQ = (const float*)d_in[1];
    const float* WK = (const float*)d_in[2];
    const float* WV = (const float*)d_in[3];
    float* out = (float*)d_out;

    qk_kernel<<<NROW / 8, 256>>>(x, WQ, WK);
    argmax_kernel<<<dim3(80, BB), 128>>>();
    decode_kernel<<<NROW / 256, 256>>>();
    vrows_kernel<<<444, 256>>>(WV, x);
    gather_kernel<<<NROW / 8, 256>>>(out);
}

// round 15
// speedup vs baseline: 1.0480x; 1.0480x over previous
#include <cuda_runtime.h>
#include <math_constants.h>

#define BB 4
#define TT 4096
#define DD 1024
#define NROW (BB*TT)          // 16384

typedef unsigned long long u64;

// ---- scratch (device globals: no allocations allowed) ----
__device__ float2 g_Q[NROW];
__device__ float2 g_K[NROW];
__device__ unsigned long long g_best64[NROW]; // (ordered(score)<<32)|~s
__device__ int    g_idx[NROW];      // flattened source row b*T + argmax_s
__device__ int    g_mark[NROW];
__device__ int    g_slot[NROW];     // src row -> compact slot
__device__ int    g_list[NROW];
__device__ int    g_count;
__device__ float  g_Vc[(size_t)NROW * DD];  // compact V rows (slot-major)

static const unsigned FULL = 0xffffffffu;

__device__ __forceinline__ unsigned ord_f32(float x) {
    unsigned u = __float_as_uint(x);
    return (u & 0x80000000u) ? ~u : (u | 0x80000000u);
}

// packed f32x2 helpers (sm_103a; PTX-only)
__device__ __forceinline__ u64 fma2(u64 a, u64 b, u64 c) {
    u64 d;
    asm("fma.rn.f32x2 %0, %1, %2, %3;" : "=l"(d) : "l"(a), "l"(b), "l"(c));
    return d;
}
__device__ __forceinline__ u64 mul2(u64 a, u64 b) {
    u64 d;
    asm("mul.rn.f32x2 %0, %1, %2;" : "=l"(d) : "l"(a), "l"(b));
    return d;
}
__device__ __forceinline__ u64 pack2(float lo, float hi) {
    u64 d;
    asm("mov.b64 %0, {%1, %2};" : "=l"(d) : "f"(lo), "f"(hi));
    return d;
}
__device__ __forceinline__ void unpack2(u64 p, float& lo, float& hi) {
    asm("mov.b64 {%0, %1}, %2;" : "=f"(lo), "=f"(hi) : "l"(p));
}

// ---------------- kernel 1: Q,K projection (+ fused scratch init) ----------
__global__ void qk_kernel(const float* __restrict__ x,
                          const float* __restrict__ WQ,
                          const float* __restrict__ WK) {
    __shared__ float4 swq0[256], swq1[256], swk0[256], swk1[256];
    const float4* WQ4 = (const float4*)WQ;
    const float4* WK4 = (const float4*)WK;
    int tid = threadIdx.x;
    swq0[tid] = WQ4[tid];
    swq1[tid] = WQ4[256 + tid];
    swk0[tid] = WK4[tid];
    swk1[tid] = WK4[256 + tid];
    __syncthreads();

    int warp = tid >> 5, lane = tid & 31;
    int row = blockIdx.x * 8 + warp;           // b*T + t
    const float4* x4 = (const float4*)x + (size_t)row * 256;

    float q0 = 0.f, q1 = 0.f, k0 = 0.f, k1 = 0.f;
#pragma unroll
    for (int j = 0; j < 8; ++j) {
        int d = lane + j * 32;
        float4 xv = x4[d];
        float4 a = swq0[d], b = swq1[d], c = swk0[d], e = swk1[d];
        q0 += xv.x*a.x + xv.y*a.y + xv.z*a.z + xv.w*a.w;
        q1 += xv.x*b.x + xv.y*b.y + xv.z*b.z + xv.w*b.w;
        k0 += xv.x*c.x + xv.y*c.y + xv.z*c.z + xv.w*c.w;
        k1 += xv.x*e.x + xv.y*e.y + xv.z*e.z + xv.w*e.w;
    }
#pragma unroll
    for (int off = 16; off; off >>= 1) {
        q0 += __shfl_xor_sync(FULL, q0, off);
        q1 += __shfl_xor_sync(FULL, q1, off);
        k0 += __shfl_xor_sync(FULL, k0, off);
        k1 += __shfl_xor_sync(FULL, k1, off);
    }
    if (lane == 0) {
        g_Q[row] = make_float2(q0, q1);
        g_K[row] = make_float2(k0, k1);
        g_mark[row] = 0;
        g_best64[row] = 0ull;                  // < any real score encoding
        if (row == 0) g_count = 0;
    }
}

// ---------------- kernel 2: argmax, packed-max + 2-phase index --------------
// Unit = (128-t tile, 1024-s chunk), grid (80, BB), 128 thr (as R7).
// K staged pair-transposed: ksp[i] = (x_{2i}, x_{2i+1}, y_{2i}, y_{2i+1}).
// Phase 1: mul2+fma2 + 2 FMNMX per pair (max only) + cumulative 64-s block
// maxes. Phase 2: first block whose cum == best, scalar rescan <=64 s with
// __fmul_rn/__fmaf_rn (bitwise == packed) -> first-occurrence index.
__global__ void __launch_bounds__(128) argmax_kernel() {
    __shared__ float4 ksp[512];    // 8 KB
    int b = blockIdx.y;
    int u = blockIdx.x, g = 0, base = 0;
    while (u >= base + 8 * (g + 1)) { base += 8 * (g + 1); ++g; }
    int r = u - base;
    int ti = g * 8 + r / (g + 1);
    int chunk = r % (g + 1);
    int t0 = ti * 128, s0 = chunk * 1024;

    const float4* K4 = (const float4*)(g_K + b * TT + s0);
#pragma unroll
    for (int j = 0; j < 4; ++j) {
        float4 v = K4[threadIdx.x + j * 128];  // (x0,y0,x1,y1) of pair
        ksp[threadIdx.x + j * 128] = make_float4(v.x, v.z, v.y, v.w);
    }
    __syncthreads();

    int t = t0 + threadIdx.x;
    float2 q = g_Q[b * TT + t];
    int s_limit = t - s0 + 1;
    if (s_limit > 1024) s_limit = 1024;
    int np = s_limit >> 1;                     // full pairs

    u64 qx2 = pack2(q.x, q.x);
    u64 qy2 = pack2(q.y, q.y);
    const ulonglong2* kp2 = (const ulonglong2*)ksp;
    const float* kf = (const float*)ksp;

    float m0 = -CUDART_INF_F, m1 = -CUDART_INF_F;
    float bm[16];                              // cum max per 32-pair block
    int i = 0;
#pragma unroll
    for (int blk = 0; blk < 16; ++blk) {
        int iend = (blk + 1) * 32; if (iend > np) iend = np;
#pragma unroll 4
        for (; i < iend; ++i) {
            ulonglong2 p = kp2[i];             // .x=(x_e,x_o) .y=(y_e,y_o)
            u64 sc2 = fma2(qy2, p.y, mul2(qx2, p.x));
            float lo, hi; unpack2(sc2, lo, hi);
            m0 = fmaxf(m0, lo);
            m1 = fmaxf(m1, hi);
        }
        bm[blk] = fmaxf(m0, m1);
    }
    float best = fmaxf(m0, m1);

    int bi = -1;
    if (s_limit & 1) {                         // odd tail element s = s0+2*np
        float xv = kf[np * 4 + 0];
        float yv = kf[np * 4 + 2];
        float sct = __fmaf_rn(q.y, yv, __fmul_rn(q.x, xv));
        if (sct > best) { best = sct; bi = s0 + (np << 1); }
    }
    if (bi < 0) {
        int blk = 0;
        for (; blk < 15; ++blk)
            if (bm[blk] == best) break;        // first block reaching best
        int sl = blk * 64;
        int send = sl + 64; if (send > s_limit) send = s_limit;
        for (; sl < send; ++sl) {
            int pi = sl >> 1, off = sl & 1;
            float xv = kf[pi * 4 + off];
            float yv = kf[pi * 4 + 2 + off];
            float sc = __fmaf_rn(q.y, yv, __fmul_rn(q.x, xv));
            if (sc == best) { bi = s0 + sl; break; }
        }
    }

    unsigned long long enc =
        ((unsigned long long)ord_f32(best) << 32) | (unsigned)(~bi);
    atomicMax(&g_best64[b * TT + t], enc);
}

// ---------------- kernel 2b: decode argmax + build unique list -------------
// Warp-dedup (__match_any_sync) + mark prefilter.
__global__ void decode_kernel() {
    int i = blockIdx.x * 256 + threadIdx.x;
    unsigned long long enc = g_best64[i];
    int s = (int)(~(unsigned)(enc & 0xffffffffull));
    int src = (i & ~(TT - 1)) | s;
    g_idx[i] = src;

    unsigned peers = __match_any_sync(FULL, src);
    int leader = __ffs(peers) - 1;
    if ((threadIdx.x & 31) == leader) {
        if (g_mark[src] == 0 && atomicExch(&g_mark[src], 1) == 0) {
            int p = atomicAdd(&g_count, 1);
            g_list[p] = src;
            g_slot[src] = p;                   // read only by later kernels
        }
    }
}

// ---------------- kernel 3: V rows, 4 rows x 4 e per warp (R12 exact) ------
#define RG 4
__global__ void __launch_bounds__(256) vrows_kernel(const float* __restrict__ WV,
                                                    const float* __restrict__ x) {
    __shared__ float4 xs[RG * 256];            // 16 KB
    int cnt = g_count;
    int ngrp = (cnt + RG - 1) / RG;
    int items = ngrp * 32;                     // 32 e-tiles of 32
    int warp = threadIdx.x >> 5, lane = threadIdx.x & 31;
    int tid = threadIdx.x;

    for (int it = blockIdx.x; it < items; it += gridDim.x) {
        int grp  = it >> 5;                    // / 32
        int tile = it & 31;
        int ui0  = grp * RG;

        __syncthreads();                       // protect xs reuse
#pragma unroll
        for (int j = 0; j < 4; ++j) {          // 1024 float4 by 256 threads
            int f = tid + j * 256;
            int rr = f >> 8, c = f & 255;
            int ui = ui0 + rr;
            int row = g_list[(ui < cnt) ? ui : 0];
            xs[f] = ((const float4*)x)[(size_t)row * 256 + c];
        }
        __syncthreads();

        int e0 = tile * 32 + warp * 4;
        const float4* wp0 = (const float4*)WV + (size_t)(e0 + 0) * 256;
        const float4* wp1 = (const float4*)WV + (size_t)(e0 + 1) * 256;
        const float4* wp2 = (const float4*)WV + (size_t)(e0 + 2) * 256;
        const float4* wp3 = (const float4*)WV + (size_t)(e0 + 3) * 256;

        float a[16];                           // a[r*4+e]
#pragma unroll
        for (int k = 0; k < 16; ++k) a[k] = 0.f;

#pragma unroll
        for (int j = 0; j < 8; ++j) {
            int d = lane + j * 32;
            float4 w0 = __ldg(&wp0[d]);
            float4 w1 = __ldg(&wp1[d]);
            float4 w2 = __ldg(&wp2[d]);
            float4 w3 = __ldg(&wp3[d]);
#pragma unroll
            for (int rr = 0; rr < RG; ++rr) {
                float4 xv = xs[rr * 256 + d];
                a[rr*4+0] += w0.x*xv.x + w0.y*xv.y + w0.z*xv.z + w0.w*xv.w;
                a[rr*4+1] += w1.x*xv.x + w1.y*xv.y + w1.z*xv.z + w1.w*xv.w;
                a[rr*4+2] += w2.x*xv.x + w2.y*xv.y + w2.z*xv.z + w2.w*xv.w;
                a[rr*4+3] += w3.x*xv.x + w3.y*xv.y + w3.z*xv.z + w3.w*xv.w;
            }
        }

        // butterfly: off=16 full-exchange on all 16, then distribute 16 values
        // over lanes (31 SHFL total). Lane l<16 ends with pair l.
#pragma unroll
        for (int i2 = 0; i2 < 16; ++i2)
            a[i2] += __shfl_xor_sync(FULL, a[i2], 16);
#pragma unroll
        for (int off = 8; off; off >>= 1) {
#pragma unroll
            for (int i2 = 0; i2 < off; ++i2) {
                float lo = a[i2], hi = a[i2 + off];
                float mine = (lane & off) ? hi : lo;
                float send = (lane & off) ? lo : hi;
                float other = __shfl_xor_sync(FULL, send, off);
                a[i2] = mine + other;
            }
        }

        if (lane < 16) {
            int rr = lane >> 2, e = lane & 3;
            int ui = ui0 + rr;
            if (ui < cnt)
                g_Vc[(size_t)ui * DD + e0 + e] = a[0];
        }
    }
}

// ---------------- kernel 4: gather to output ----------------
// Warp copies one 4KB row from compact (L2-resident) V; streaming stores.
__global__ void gather_kernel(float* __restrict__ out) {
    int warp = threadIdx.x >> 5, lane = threadIdx.x & 31;
    int r = blockIdx.x * 8 + warp;          // destination row b*T + t
    int slot = g_slot[g_idx[r]];
    const float4* v4 = (const float4*)g_Vc + (size_t)slot * 256;
    float4* o4 = (float4*)out + (size_t)r * 256;
#pragma unroll
    for (int j = 0; j < 8; ++j) {
        float4 v = __ldg(&v4[lane + j * 32]);
        __stcs(&o4[lane + j * 32], v);
    }
}

extern "C" void kernel_launch(void* const* d_in, const int* in_sizes, int n_in,
                              void* d_out, int out_size) {
    const float* x  = (const float*)d_in[0];
    const float* WQ = (const float*)d_in[1];
    const float* WK = (const float*)d_in[2];
    const float* WV = (const float*)d_in[3];
    float* out = (float*)d_out;

    qk_kernel<<<NROW / 8, 256>>>(x, WQ, WK);
    argmax_kernel<<<dim3(80, BB), 128>>>();
    decode_kernel<<<NROW / 256, 256>>>();
    vrows_kernel<<<444, 256>>>(WV, x);
    gather_kernel<<<NROW / 8, 256>>>(out);
}

// round 16
// speedup vs baseline: 1.2235x; 1.1675x over previous
#include <cuda_runtime.h>
#include <math_constants.h>

#define BB 4
#define TT 4096
#define DD 1024
#define NROW (BB*TT)          // 16384

// ---- scratch (device globals: no allocations allowed) ----
__device__ float2 g_Q[NROW];
__device__ float2 g_K[NROW];
__device__ unsigned long long g_best64[NROW]; // (ordered(score)<<32)|~s
__device__ int    g_idx[NROW];      // flattened source row b*T + argmax_s
__device__ int    g_mark[NROW];
__device__ int    g_slot[NROW];     // src row -> compact slot
__device__ int    g_list[NROW];
__device__ int    g_count;
__device__ float  g_Vc[(size_t)NROW * DD];  // compact V rows (slot-major)

static const unsigned FULL = 0xffffffffu;

__device__ __forceinline__ unsigned ord_f32(float x) {
    unsigned u = __float_as_uint(x);
    return (u & 0x80000000u) ? ~u : (u | 0x80000000u);
}

// ---------------- kernel 1: Q,K projection (+ fused scratch init) ----------
__global__ void qk_kernel(const float* __restrict__ x,
                          const float* __restrict__ WQ,
                          const float* __restrict__ WK) {
    __shared__ float4 swq0[256], swq1[256], swk0[256], swk1[256];
    const float4* WQ4 = (const float4*)WQ;
    const float4* WK4 = (const float4*)WK;
    int tid = threadIdx.x;
    swq0[tid] = WQ4[tid];
    swq1[tid] = WQ4[256 + tid];
    swk0[tid] = WK4[tid];
    swk1[tid] = WK4[256 + tid];
    __syncthreads();

    int warp = tid >> 5, lane = tid & 31;
    int row = blockIdx.x * 8 + warp;           // b*T + t
    const float4* x4 = (const float4*)x + (size_t)row * 256;

    float q0 = 0.f, q1 = 0.f, k0 = 0.f, k1 = 0.f;
#pragma unroll
    for (int j = 0; j < 8; ++j) {
        int d = lane + j * 32;
        float4 xv = __ldcs(&x4[d]);            // streaming: x read once here
        float4 a = swq0[d], b = swq1[d], c = swk0[d], e = swk1[d];
        q0 += xv.x*a.x + xv.y*a.y + xv.z*a.z + xv.w*a.w;
        q1 += xv.x*b.x + xv.y*b.y + xv.z*b.z + xv.w*b.w;
        k0 += xv.x*c.x + xv.y*c.y + xv.z*c.z + xv.w*c.w;
        k1 += xv.x*e.x + xv.y*e.y + xv.z*e.z + xv.w*e.w;
    }
#pragma unroll
    for (int off = 16; off; off >>= 1) {
        q0 += __shfl_xor_sync(FULL, q0, off);
        q1 += __shfl_xor_sync(FULL, q1, off);
        k0 += __shfl_xor_sync(FULL, k0, off);
        k1 += __shfl_xor_sync(FULL, k1, off);
    }
    if (lane == 0) {
        g_Q[row] = make_float2(q0, q1);
        g_K[row] = make_float2(k0, k1);
        g_mark[row] = 0;
        g_best64[row] = 0ull;                  // < any real score encoding
        if (row == 0) g_count = 0;
    }
}

// ---------------- kernel 2: argmax, tile x 512-chunk units ----------------
// Unit = (128-t tile, 512-s chunk): 144 units/batch, grid (144, BB), 128 thr
// -> ~3.9 blocks/SM (was 2.2 at chunk=1024): more warps to hide LDS chain.
// Group g (0..7) holds 4 tiles x (g+1) chunks. Same per-score code as R7.
// Merge via atomicMax of (ordered(score)<<32)|~s -> max score, min s on tie.
__global__ void __launch_bounds__(128) argmax_kernel() {
    __shared__ float2 ks[512];     // 4 KB
    int b = blockIdx.y;
    int u = blockIdx.x, g = 0, base = 0;
    while (u >= base + 4 * (g + 1)) { base += 4 * (g + 1); ++g; }
    int r = u - base;
    int ti = g * 4 + r / (g + 1);
    int chunk = r % (g + 1);
    int t0 = ti * 128, s0 = chunk * 512;

    const float4* K4 = (const float4*)(g_K + b * TT + s0);
#pragma unroll
    for (int j = 0; j < 2; ++j)
        ((float4*)ks)[threadIdx.x + j * 128] = K4[threadIdx.x + j * 128];
    __syncthreads();

    int t = t0 + threadIdx.x;
    float2 q = g_Q[b * TT + t];
    int s_limit = t - s0 + 1;
    if (s_limit > 512) s_limit = 512;

    float best = -CUDART_INF_F;
    int bi = 0;
    for (int s = 0; s < s_limit; ++s) {        // ascending + strict > = first occ.
        float2 k = ks[s];
        float sc = k.x * q.x + k.y * q.y;
        if (sc > best) { best = sc; bi = s0 + s; }
    }
    unsigned long long enc =
        ((unsigned long long)ord_f32(best) << 32) | (unsigned)(~bi);
    atomicMax(&g_best64[b * TT + t], enc);
}

// ---------------- kernel 2b: decode argmax + build unique list -------------
// Warp-dedup (__match_any_sync) + mark prefilter.
__global__ void decode_kernel() {
    int i = blockIdx.x * 256 + threadIdx.x;
    unsigned long long enc = g_best64[i];
    int s = (int)(~(unsigned)(enc & 0xffffffffull));
    int src = (i & ~(TT - 1)) | s;
    g_idx[i] = src;

    unsigned peers = __match_any_sync(FULL, src);
    int leader = __ffs(peers) - 1;
    if ((threadIdx.x & 31) == leader) {
        if (g_mark[src] == 0 && atomicExch(&g_mark[src], 1) == 0) {
            int p = atomicAdd(&g_count, 1);
            g_list[p] = src;
            g_slot[src] = p;                   // read only by later kernels
        }
    }
}

// ---------------- kernel 3: V rows, 4 rows x 4 e per warp (R12 exact) ------
#define RG 4
__global__ void __launch_bounds__(256) vrows_kernel(const float* __restrict__ WV,
                                                    const float* __restrict__ x) {
    __shared__ float4 xs[RG * 256];            // 16 KB
    int cnt = g_count;
    int ngrp = (cnt + RG - 1) / RG;
    int items = ngrp * 32;                     // 32 e-tiles of 32
    int warp = threadIdx.x >> 5, lane = threadIdx.x & 31;
    int tid = threadIdx.x;

    for (int it = blockIdx.x; it < items; it += gridDim.x) {
        int grp  = it >> 5;                    // / 32
        int tile = it & 31;
        int ui0  = grp * RG;

        __syncthreads();                       // protect xs reuse
#pragma unroll
        for (int j = 0; j < 4; ++j) {          // 1024 float4 by 256 threads
            int f = tid + j * 256;
            int rr = f >> 8, c = f & 255;
            int ui = ui0 + rr;
            int row = g_list[(ui < cnt) ? ui : 0];
            xs[f] = ((const float4*)x)[(size_t)row * 256 + c];
        }
        __syncthreads();

        int e0 = tile * 32 + warp * 4;
        const float4* wp0 = (const float4*)WV + (size_t)(e0 + 0) * 256;
        const float4* wp1 = (const float4*)WV + (size_t)(e0 + 1) * 256;
        const float4* wp2 = (const float4*)WV + (size_t)(e0 + 2) * 256;
        const float4* wp3 = (const float4*)WV + (size_t)(e0 + 3) * 256;

        float a[16];                           // a[r*4+e]
#pragma unroll
        for (int k = 0; k < 16; ++k) a[k] = 0.f;

#pragma unroll
        for (int j = 0; j < 8; ++j) {
            int d = lane + j * 32;
            float4 w0 = __ldg(&wp0[d]);
            float4 w1 = __ldg(&wp1[d]);
            float4 w2 = __ldg(&wp2[d]);
            float4 w3 = __ldg(&wp3[d]);
#pragma unroll
            for (int rr = 0; rr < RG; ++rr) {
                float4 xv = xs[rr * 256 + d];
                a[rr*4+0] += w0.x*xv.x + w0.y*xv.y + w0.z*xv.z + w0.w*xv.w;
                a[rr*4+1] += w1.x*xv.x + w1.y*xv.y + w1.z*xv.z + w1.w*xv.w;
                a[rr*4+2] += w2.x*xv.x + w2.y*xv.y + w2.z*xv.z + w2.w*xv.w;
                a[rr*4+3] += w3.x*xv.x + w3.y*xv.y + w3.z*xv.z + w3.w*xv.w;
            }
        }

        // butterfly: off=16 full-exchange on all 16, then distribute 16 values
        // over lanes (31 SHFL total). Lane l<16 ends with pair l.
#pragma unroll
        for (int i2 = 0; i2 < 16; ++i2)
            a[i2] += __shfl_xor_sync(FULL, a[i2], 16);
#pragma unroll
        for (int off = 8; off; off >>= 1) {
#pragma unroll
            for (int i2 = 0; i2 < off; ++i2) {
                float lo = a[i2], hi = a[i2 + off];
                float mine = (lane & off) ? hi : lo;
                float send = (lane & off) ? lo : hi;
                float other = __shfl_xor_sync(FULL, send, off);
                a[i2] = mine + other;
            }
        }

        if (lane < 16) {
            int rr = lane >> 2, e = lane & 3;
            int ui = ui0 + rr;
            if (ui < cnt)
                g_Vc[(size_t)ui * DD + e0 + e] = a[0];
        }
    }
}

// ---------------- kernel 4: gather to output ----------------
// Warp copies one 4KB row from compact (L2-resident) V; streaming stores.
__global__ void gather_kernel(float* __restrict__ out) {
    int warp = threadIdx.x >> 5, lane = threadIdx.x & 31;
    int r = blockIdx.x * 8 + warp;          // destination row b*T + t
    int slot = g_slot[g_idx[r]];
    const float4* v4 = (const float4*)g_Vc + (size_t)slot * 256;
    float4* o4 = (float4*)out + (size_t)r * 256;
#pragma unroll
    for (int j = 0; j < 8; ++j) {
        float4 v = __ldg(&v4[lane + j * 32]);
        __stcs(&o4[lane + j * 32], v);
    }
}

extern "C" void kernel_launch(void* const* d_in, const int* in_sizes, int n_in,
                              void* d_out, int out_size) {
    const float* x  = (const float*)d_in[0];
    const float* WQ = (const float*)d_in[1];
    const float* WK = (const float*)d_in[2];
    const float* WV = (const float*)d_in[3];
    float* out = (float*)d_out;

    qk_kernel<<<NROW / 8, 256>>>(x, WQ, WK);
    argmax_kernel<<<dim3(144, BB), 128>>>();
    decode_kernel<<<NROW / 256, 256>>>();
    vrows_kernel<<<444, 256>>>(WV, x);
    gather_kernel<<<NROW / 8, 256>>>(out);
}

// round 17
// speedup vs baseline: 1.2594x; 1.0293x over previous
#include <cuda_runtime.h>
#include <math_constants.h>

#define BB 4
#define TT 4096
#define DD 1024
#define NROW (BB*TT)          // 16384

// ---- scratch (device globals: no allocations allowed) ----
__device__ float2 g_Q[NROW];
__device__ float2 g_K[NROW];
__device__ unsigned long long g_best64[NROW]; // (ordered(score)<<32)|~s
__device__ int    g_idx[NROW];      // flattened source row b*T + argmax_s
__device__ int    g_mark[NROW];
__device__ int    g_slot[NROW];     // src row -> compact slot
__device__ int    g_list[NROW];
__device__ int    g_count;
__device__ float  g_Vc[(size_t)NROW * DD];  // compact V rows (slot-major)

static const unsigned FULL = 0xffffffffu;

// PDL: wait until the predecessor grid's memory is visible.
#define PDL_WAIT() asm volatile("griddepcontrol.wait;" ::: "memory")

__device__ __forceinline__ unsigned ord_f32(float x) {
    unsigned u = __float_as_uint(x);
    return (u & 0x80000000u) ? ~u : (u | 0x80000000u);
}

// ---------------- kernel 1: Q,K projection (+ fused scratch init) ----------
__global__ void qk_kernel(const float* __restrict__ x,
                          const float* __restrict__ WQ,
                          const float* __restrict__ WK) {
    __shared__ float4 swq0[256], swq1[256], swk0[256], swk1[256];
    const float4* WQ4 = (const float4*)WQ;
    const float4* WK4 = (const float4*)WK;
    int tid = threadIdx.x;
    swq0[tid] = WQ4[tid];
    swq1[tid] = WQ4[256 + tid];
    swk0[tid] = WK4[tid];
    swk1[tid] = WK4[256 + tid];
    __syncthreads();

    int warp = tid >> 5, lane = tid & 31;
    int row = blockIdx.x * 8 + warp;           // b*T + t
    const float4* x4 = (const float4*)x + (size_t)row * 256;

    float q0 = 0.f, q1 = 0.f, k0 = 0.f, k1 = 0.f;
#pragma unroll
    for (int j = 0; j < 8; ++j) {
        int d = lane + j * 32;
        float4 xv = __ldcs(&x4[d]);            // streaming: x read once here
        float4 a = swq0[d], b = swq1[d], c = swk0[d], e = swk1[d];
        q0 += xv.x*a.x + xv.y*a.y + xv.z*a.z + xv.w*a.w;
        q1 += xv.x*b.x + xv.y*b.y + xv.z*b.z + xv.w*b.w;
        k0 += xv.x*c.x + xv.y*c.y + xv.z*c.z + xv.w*c.w;
        k1 += xv.x*e.x + xv.y*e.y + xv.z*e.z + xv.w*e.w;
    }
#pragma unroll
    for (int off = 16; off; off >>= 1) {
        q0 += __shfl_xor_sync(FULL, q0, off);
        q1 += __shfl_xor_sync(FULL, q1, off);
        k0 += __shfl_xor_sync(FULL, k0, off);
        k1 += __shfl_xor_sync(FULL, k1, off);
    }
    if (lane == 0) {
        g_Q[row] = make_float2(q0, q1);
        g_K[row] = make_float2(k0, k1);
        g_mark[row] = 0;
        g_best64[row] = 0ull;                  // < any real score encoding
        if (row == 0) g_count = 0;
    }
}

// ---------------- kernel 2: argmax, tile x 256-chunk units ----------------
// Unit = (128-t tile, 256-s chunk): 272 units/batch, grid (272, BB), 128 thr
// -> ~7.4 blocks/SM (29 warps/SM) hiding the LDS chain.
// Group g (0..15) = tiles {2g, 2g+1}, each with (g+1) chunks.
// Merge via atomicMax of (ordered(score)<<32)|~s -> max score, min s on tie.
__global__ void __launch_bounds__(128) argmax_kernel() {
    PDL_WAIT();
    __shared__ float2 ks[256];     // 2 KB
    int b = blockIdx.y;
    int u = blockIdx.x, g = 0, base = 0;
    while (u >= base + 2 * (g + 1)) { base += 2 * (g + 1); ++g; }
    int r = u - base;
    int ti = 2 * g + r / (g + 1);
    int chunk = r % (g + 1);
    int t0 = ti * 128, s0 = chunk * 256;

    const float4* K4 = (const float4*)(g_K + b * TT + s0);
    ((float4*)ks)[threadIdx.x] = K4[threadIdx.x];   // 128 float4 = 256 float2
    __syncthreads();

    int t = t0 + threadIdx.x;
    float2 q = g_Q[b * TT + t];
    int s_limit = t - s0 + 1;
    if (s_limit > 256) s_limit = 256;

    float best = -CUDART_INF_F;
    int bi = 0;
    for (int s = 0; s < s_limit; ++s) {        // ascending + strict > = first occ.
        float2 k = ks[s];
        float sc = k.x * q.x + k.y * q.y;
        if (sc > best) { best = sc; bi = s0 + s; }
    }
    unsigned long long enc =
        ((unsigned long long)ord_f32(best) << 32) | (unsigned)(~bi);
    atomicMax(&g_best64[b * TT + t], enc);
}

// ---------------- kernel 2b: decode argmax + build unique list -------------
// Warp-dedup (__match_any_sync) + mark prefilter.
__global__ void decode_kernel() {
    PDL_WAIT();
    int i = blockIdx.x * 256 + threadIdx.x;
    unsigned long long enc = g_best64[i];
    int s = (int)(~(unsigned)(enc & 0xffffffffull));
    int src = (i & ~(TT - 1)) | s;
    g_idx[i] = src;

    unsigned peers = __match_any_sync(FULL, src);
    int leader = __ffs(peers) - 1;
    if ((threadIdx.x & 31) == leader) {
        if (g_mark[src] == 0 && atomicExch(&g_mark[src], 1) == 0) {
            int p = atomicAdd(&g_count, 1);
            g_list[p] = src;
            g_slot[src] = p;                   // read only by later kernels
        }
    }
}

// ---------------- kernel 3: V rows, 4 rows x 4 e per warp (R12 exact) ------
#define RG 4
__global__ void __launch_bounds__(256) vrows_kernel(const float* __restrict__ WV,
                                                    const float* __restrict__ x) {
    PDL_WAIT();
    __shared__ float4 xs[RG * 256];            // 16 KB
    int cnt = g_count;
    int ngrp = (cnt + RG - 1) / RG;
    int items = ngrp * 32;                     // 32 e-tiles of 32
    int warp = threadIdx.x >> 5, lane = threadIdx.x & 31;
    int tid = threadIdx.x;

    for (int it = blockIdx.x; it < items; it += gridDim.x) {
        int grp  = it >> 5;                    // / 32
        int tile = it & 31;
        int ui0  = grp * RG;

        __syncthreads();                       // protect xs reuse
#pragma unroll
        for (int j = 0; j < 4; ++j) {          // 1024 float4 by 256 threads
            int f = tid + j * 256;
            int rr = f >> 8, c = f & 255;
            int ui = ui0 + rr;
            int row = g_list[(ui < cnt) ? ui : 0];
            xs[f] = ((const float4*)x)[(size_t)row * 256 + c];
        }
        __syncthreads();

        int e0 = tile * 32 + warp * 4;
        const float4* wp0 = (const float4*)WV + (size_t)(e0 + 0) * 256;
        const float4* wp1 = (const float4*)WV + (size_t)(e0 + 1) * 256;
        const float4* wp2 = (const float4*)WV + (size_t)(e0 + 2) * 256;
        const float4* wp3 = (const float4*)WV + (size_t)(e0 + 3) * 256;

        float a[16];                           // a[r*4+e]
#pragma unroll
        for (int k = 0; k < 16; ++k) a[k] = 0.f;

#pragma unroll
        for (int j = 0; j < 8; ++j) {
            int d = lane + j * 32;
            float4 w0 = __ldg(&wp0[d]);
            float4 w1 = __ldg(&wp1[d]);
            float4 w2 = __ldg(&wp2[d]);
            float4 w3 = __ldg(&wp3[d]);
#pragma unroll
            for (int rr = 0; rr < RG; ++rr) {
                float4 xv = xs[rr * 256 + d];
                a[rr*4+0] += w0.x*xv.x + w0.y*xv.y + w0.z*xv.z + w0.w*xv.w;
                a[rr*4+1] += w1.x*xv.x + w1.y*xv.y + w1.z*xv.z + w1.w*xv.w;
                a[rr*4+2] += w2.x*xv.x + w2.y*xv.y + w2.z*xv.z + w2.w*xv.w;
                a[rr*4+3] += w3.x*xv.x + w3.y*xv.y + w3.z*xv.z + w3.w*xv.w;
            }
        }

        // butterfly: off=16 full-exchange on all 16, then distribute 16 values
        // over lanes (31 SHFL total). Lane l<16 ends with pair l.
#pragma unroll
        for (int i2 = 0; i2 < 16; ++i2)
            a[i2] += __shfl_xor_sync(FULL, a[i2], 16);
#pragma unroll
        for (int off = 8; off; off >>= 1) {
#pragma unroll
            for (int i2 = 0; i2 < off; ++i2) {
                float lo = a[i2], hi = a[i2 + off];
                float mine = (lane & off) ? hi : lo;
                float send = (lane & off) ? lo : hi;
                float other = __shfl_xor_sync(FULL, send, off);
                a[i2] = mine + other;
            }
        }

        if (lane < 16) {
            int rr = lane >> 2, e = lane & 3;
            int ui = ui0 + rr;
            if (ui < cnt)
                g_Vc[(size_t)ui * DD + e0 + e] = a[0];
        }
    }
}

// ---------------- kernel 4: gather to output ----------------
// Warp copies one 4KB row from compact (L2-resident) V; streaming stores.
__global__ void gather_kernel(float* __restrict__ out) {
    PDL_WAIT();
    int warp = threadIdx.x >> 5, lane = threadIdx.x & 31;
    int r = blockIdx.x * 8 + warp;          // destination row b*T + t
    int slot = g_slot[g_idx[r]];
    const float4* v4 = (const float4*)g_Vc + (size_t)slot * 256;
    float4* o4 = (float4*)out + (size_t)r * 256;
#pragma unroll
    for (int j = 0; j < 8; ++j) {
        float4 v = __ldg(&v4[lane + j * 32]);
        __stcs(&o4[lane + j * 32], v);
    }
}

// PDL launch helper: programmatic stream serialization attribute.
template <typename K, typename... Args>
static void launch_pdl(dim3 grid, dim3 block, K kernel, Args... args) {
    cudaLaunchAttribute attr;
    attr.id = cudaLaunchAttributeProgrammaticStreamSerialization;
    attr.val.programmaticStreamSerializationAllowed = 1;
    cudaLaunchConfig_t cfg = {};
    cfg.gridDim = grid;
    cfg.blockDim = block;
    cfg.dynamicSmemBytes = 0;
    cfg.stream = 0;
    cfg.attrs = &attr;
    cfg.numAttrs = 1;
    cudaLaunchKernelEx(&cfg, kernel, args...);
}

extern "C" void kernel_launch(void* const* d_in, const int* in_sizes, int n_in,
                              void* d_out, int out_size) {
    const float* x  = (const float*)d_in[0];
    const float* WQ = (const float*)d_in[1];
    const float* WK = (const float*)d_in[2];
    const float* WV = (const float*)d_in[3];
    float* out = (float*)d_out;

    qk_kernel<<<NROW / 8, 256>>>(x, WQ, WK);
    launch_pdl(dim3(272, BB), dim3(128), argmax_kernel);
    launch_pdl(dim3(NROW / 256), dim3(256), decode_kernel);
    launch_pdl(dim3(444), dim3(256), vrows_kernel, WV, x);
    launch_pdl(dim3(NROW / 8), dim3(256), gather_kernel, out);
}